// round 7
// baseline (speedup 1.0000x reference)
#include <cuda_runtime.h>
#include <cstdint>

// IndexAddInplace as a GATHER: out[j] = x[j] + sum_{i: idx[i]==j} src[i]
// x: [N_DST=100000, D=512] f32, idx: [N_SRC=200000] int64/int32 (detected),
// src: [N_SRC, D] f32.
//
// SINGLE persistent kernel (one launch):
//   phase 1: build inverted index — K inline slots per dst row (atomicAdd
//            counter) + linked-list spill (i+1 encoded, 0 = end, zero-init OK).
//   ----- software grid barrier (self-resetting across graph replays) -----
//   phase 2: gather — one WARP per row (4 float4/lane), independent LDG.128s
//            from the inline slots (MLP ~= 4*(1+cnt)), then self-clean the
//            row's index state behind a __syncwarp().
// Grid = 1184 blocks of 128 thr, __launch_bounds__(128,8) forces <=64 regs
// => all blocks guaranteed co-resident (148+ SMs x 8) => barrier is safe.
// Traffic floor: 205MB x-read + 410MB src-read + 205MB out-write (+~4MB index).

#define MAX_DST 100000
#define MAX_SRC 200000
#define K_SLOTS 6
#define NBLOCKS 1184            // 148 * 8, co-resident by construction
#define NTHREADS 128

__device__ int g_cnt[MAX_DST];               // zero-init = empty
__device__ int g_slot[MAX_DST * K_SLOTS];
__device__ int g_head[MAX_DST];              // stores i+1; 0 = end (zero-init OK)
__device__ int g_next[MAX_SRC];              // stores i+1 links
__device__ unsigned g_bar_arrive;            // zero-init; reset by releaser
__device__ volatile unsigned g_bar_gen;      // generation counter (monotone)

__global__ void __launch_bounds__(NTHREADS, 8)
fused_kernel(const void* __restrict__ idx_raw,
             const float4* __restrict__ x,
             const float4* __restrict__ src,
             float4* __restrict__ out,
             int n_src, int n_dst, int dv) {
    const int tid = threadIdx.x;
    const int gtid = blockIdx.x * NTHREADS + tid;
    const int gstride = NBLOCKS * NTHREADS;

    // ---- idx dtype detect (per block, 256-odd-word sample, L2 broadcast) ----
    // int64 idx with values < 2^31: ALL odd 32-bit words are 0 (LE).
    // int32 idx: odd words are random dst indices; P(all 256 == 0) ~ 0.
    int local = 0;
    #pragma unroll
    for (int k = 0; k < 2; k++) {
        int w = tid + k * NTHREADS;
        if (2 * w + 1 < n_src) local |= ((const int*)idx_raw)[2 * w + 1];
    }
    const int is64 = !__syncthreads_or(local != 0);

    // ---- phase 1: build inverted index ----
    for (int i = gtid; i < n_src; i += gstride) {
        int d;
        if (is64) d = (int)((const long long*)idx_raw)[i];
        else      d = ((const int*)idx_raw)[i];
        int pos = atomicAdd(&g_cnt[d], 1);
        if (pos < K_SLOTS) g_slot[d * K_SLOTS + pos] = i;
        else               g_next[i] = atomicExch(&g_head[d], i + 1);
    }

    // ---- grid barrier (all 1184 blocks are resident) ----
    __threadfence();                         // publish phase-1 writes
    __syncthreads();
    if (tid == 0) {
        unsigned gen = g_bar_gen;
        if (atomicAdd(&g_bar_arrive, 1) == NBLOCKS - 1) {
            atomicExch(&g_bar_arrive, 0);    // ready for next graph replay
            __threadfence();
            g_bar_gen = gen + 1;             // release
        } else {
            while (g_bar_gen == gen) { }     // spin (short: build is balanced)
        }
    }
    __syncthreads();
    __threadfence();                         // acquire phase-1 writes

    // ---- phase 2: gather, one warp per row ----
    const int lane = tid & 31;
    const int warp0 = gtid >> 5;
    const int nwarps = gstride >> 5;         // 4736

    for (int j = warp0; j < n_dst; j += nwarps) {
        const int n = __ldg(&g_cnt[j]);      // warp-uniform, L2-resident
        const int m = n < K_SLOTS ? n : K_SLOTS;

        const size_t rbase = (size_t)j * dv + lane;   // dv = 128

        float4 acc[4];
        #pragma unroll
        for (int q = 0; q < 4; q++)
            acc[q] = __ldcs(&x[rbase + q * 32]);      // independent streaming

        int ids[K_SLOTS];
        #pragma unroll
        for (int k = 0; k < K_SLOTS; k++)
            if (k < m) ids[k] = __ldg(&g_slot[j * K_SLOTS + k]);

        #pragma unroll
        for (int k = 0; k < K_SLOTS; k++) {
            if (k < m) {
                const size_t sbase = (size_t)ids[k] * dv + lane;
                #pragma unroll
                for (int q = 0; q < 4; q++) {
                    float4 v = __ldcs(&src[sbase + q * 32]);
                    acc[q].x += v.x; acc[q].y += v.y;
                    acc[q].z += v.z; acc[q].w += v.w;
                }
            }
        }

        // Rare spill (>K sources, ~0.45% of rows): walk i+1-encoded chain.
        if (n > K_SLOTS) {
            for (int v1 = __ldg(&g_head[j]); v1 != 0; v1 = __ldg(&g_next[v1 - 1])) {
                const size_t sbase = (size_t)(v1 - 1) * dv + lane;
                #pragma unroll
                for (int q = 0; q < 4; q++) {
                    float4 v = __ldcs(&src[sbase + q * 32]);
                    acc[q].x += v.x; acc[q].y += v.y;
                    acc[q].z += v.z; acc[q].w += v.w;
                }
            }
        }

        #pragma unroll
        for (int q = 0; q < 4; q++)
            __stcs(&out[rbase + q * 32], acc[q]);

        // Whole warp has consumed this row's state before lane 0 resets it.
        __syncwarp();
        if (lane == 0) {
            g_cnt[j] = 0;
            if (n > K_SLOTS) g_head[j] = 0;
        }
    }
}

extern "C" void kernel_launch(void* const* d_in, const int* in_sizes, int n_in,
                              void* d_out, int out_size) {
    // Inputs: x [N_DST*D] f32, idx [N_SRC], src [N_SRC*D] f32
    const float* x   = (const float*)d_in[0];
    const void*  idx = (const void*)d_in[1];
    const float* src = (const float*)d_in[2];
    float* out = (float*)d_out;

    const int n_src = in_sizes[1];             // 200000
    const int d     = in_sizes[2] / n_src;     // 512
    const int n_dst = out_size / d;            // 100000
    const int dv    = d / 4;                   // 128 float4/row

    fused_kernel<<<NBLOCKS, NTHREADS>>>(idx, (const float4*)x,
                                        (const float4*)src, (float4*)out,
                                        n_src, n_dst, dv);
}

// round 8
// speedup vs baseline: 1.0652x; 1.0652x over previous
#include <cuda_runtime.h>
#include <cstdint>

// IndexAddInplace as a GATHER: out[j] = x[j] + sum_{i: idx[i]==j} src[i]
// x: [N_DST=100000, D=512] f32, idx: [N_SRC=200000] int64/int32 (detected),
// src: [N_SRC, D] f32.
//
// build : K inline slots per dst row (atomicAdd counter) + linked-list spill
//         (i+1 encoded, 0 = end => zero-init IS the empty state).
// gather: one WARP per row (4 float4/lane), launched with PROGRAMMATIC
//         DEPENDENT LAUNCH — its blocks start while build is still running,
//         prefetch the build-independent x row, then cudaGridDependencySynchronize()
//         before reading the index. Hides build + launch gap under free DRAM BW.
//         Self-cleans cnt/head behind __syncwarp() (warp-private state).
// Traffic floor: 205MB x-read + 410MB src-read + 205MB out-write (+~4MB index).

#define MAX_DST 100000
#define MAX_SRC 200000
#define K_SLOTS 6
#define DETECT_WORDS 512    // odd-word sample for dtype detection

__device__ int g_cnt[MAX_DST];               // zero-init = empty
__device__ int g_slot[MAX_DST * K_SLOTS];
__device__ int g_head[MAX_DST];              // stores i+1; 0 = end (zero-init OK)
__device__ int g_next[MAX_SRC];              // stores i+1 links

// ---- 1. build inverted index (exact grid: one element per thread) ----
// Per-block dtype detect: int64 idx with values < 2^31 has ALL odd 32-bit
// words == 0 (LE); int32 idx has random dst indices there (P(all 0) ~ 0).
__global__ void build_kernel(const void* __restrict__ idx_raw, int n_src) {
    const int* idx32 = (const int*)idx_raw;
    int local = 0;
    #pragma unroll
    for (int k = 0; k < DETECT_WORDS / 256; k++) {
        int w = threadIdx.x + k * 256;
        if (2 * w + 1 < n_src) local |= idx32[2 * w + 1];
    }
    const int is64 = !__syncthreads_or(local != 0);

    int i = blockIdx.x * blockDim.x + threadIdx.x;
    if (i >= n_src) return;

    int d;
    if (is64) d = (int)((const long long*)idx_raw)[i];
    else      d = idx32[i];

    int pos = atomicAdd(&g_cnt[d], 1);
    if (pos < K_SLOTS) g_slot[d * K_SLOTS + pos] = i;
    else               g_next[i] = atomicExch(&g_head[d], i + 1);
}

// ---- 2. gather: one WARP per row; lane handles cols c, c+32, c+64, c+96 ----
__global__ void __launch_bounds__(128)
gather_kernel(const float4* __restrict__ x,
              const float4* __restrict__ src,
              float4* __restrict__ out,
              int dv, int n_dst) {
    const int warp_id = (blockIdx.x * blockDim.x + threadIdx.x) >> 5;
    const int lane = threadIdx.x & 31;
    const bool active = warp_id < n_dst;
    const int j = active ? warp_id : 0;

    const size_t rbase = (size_t)j * dv + lane;  // dv = 128, 4 chunks of 32

    // Prefetch x row — independent of the build kernel's output. With PDL,
    // these loads execute while build is still running (free bandwidth).
    float4 acc[4];
    #pragma unroll
    for (int q = 0; q < 4; q++)
        acc[q] = __ldcs(&x[rbase + q * 32]);

    // Wait for the build kernel to complete before touching the index.
    cudaGridDependencySynchronize();

    if (!active) return;

    const int n = __ldg(&g_cnt[j]);              // warp-uniform, L2-resident
    const int m = n < K_SLOTS ? n : K_SLOTS;

    int ids[K_SLOTS];
    #pragma unroll
    for (int k = 0; k < K_SLOTS; k++)
        if (k < m) ids[k] = __ldg(&g_slot[j * K_SLOTS + k]);

    #pragma unroll
    for (int k = 0; k < K_SLOTS; k++) {
        if (k < m) {
            const size_t sbase = (size_t)ids[k] * dv + lane;
            #pragma unroll
            for (int q = 0; q < 4; q++) {
                float4 v = __ldcs(&src[sbase + q * 32]);
                acc[q].x += v.x; acc[q].y += v.y;
                acc[q].z += v.z; acc[q].w += v.w;
            }
        }
    }

    // Rare spill (>K sources, ~0.45% of rows): walk the i+1-encoded chain.
    if (n > K_SLOTS) {
        for (int v1 = __ldg(&g_head[j]); v1 != 0; v1 = __ldg(&g_next[v1 - 1])) {
            const size_t sbase = (size_t)(v1 - 1) * dv + lane;
            #pragma unroll
            for (int q = 0; q < 4; q++) {
                float4 v = __ldcs(&src[sbase + q * 32]);
                acc[q].x += v.x; acc[q].y += v.y;
                acc[q].z += v.z; acc[q].w += v.w;
            }
        }
    }

    #pragma unroll
    for (int q = 0; q < 4; q++)
        __stcs(&out[rbase + q * 32], acc[q]);

    // Whole warp has consumed this row's state before lane 0 resets it.
    __syncwarp();
    if (lane == 0) {
        g_cnt[j] = 0;
        if (n > K_SLOTS) g_head[j] = 0;
    }
}

extern "C" void kernel_launch(void* const* d_in, const int* in_sizes, int n_in,
                              void* d_out, int out_size) {
    // Inputs: x [N_DST*D] f32, idx [N_SRC], src [N_SRC*D] f32
    const float* x   = (const float*)d_in[0];
    const void*  idx = (const void*)d_in[1];
    const float* src = (const float*)d_in[2];
    float* out = (float*)d_out;

    const int n_src = in_sizes[1];             // 200000
    const int d     = in_sizes[2] / n_src;     // 512
    const int n_dst = out_size / d;            // 100000
    const int dv    = d / 4;                   // 128 float4/row

    build_kernel<<<(n_src + 255) / 256, 256>>>(idx, n_src);

    // Gather with Programmatic Dependent Launch: blocks may start while
    // build is running; device code gates on cudaGridDependencySynchronize().
    const int rows_per_block = 128 / 32;       // 4 warps = 4 rows
    cudaLaunchConfig_t cfg = {};
    cfg.gridDim  = dim3((n_dst + rows_per_block - 1) / rows_per_block, 1, 1);
    cfg.blockDim = dim3(128, 1, 1);
    cfg.dynamicSmemBytes = 0;
    cfg.stream = 0;
    cudaLaunchAttribute attr[1];
    attr[0].id = cudaLaunchAttributeProgrammaticStreamSerialization;
    attr[0].val.programmaticStreamSerializationAllowed = 1;
    cfg.attrs = attr;
    cfg.numAttrs = 1;
    cudaLaunchKernelEx(&cfg, gather_kernel,
                       (const float4*)x, (const float4*)src, (float4*)out,
                       dv, n_dst);
}